// round 12
// baseline (speedup 1.0000x reference)
#include <cuda_runtime.h>

#define N_NODES   100000
#define N_EDGES   3200000
#define N_FEAT    128
#define EMBED     20
#define N_CLASSES 10
#define N_GRAPHS  64
#define R_POOL    16
#define SLOTS     96           // padded CSR capacity; P(deg>=96) ~ e^-41 (11 sigma)
#define YPAD      32           // y row padded to 32 floats = 128 B = 1 cache line

#define CNT_SCALE 1048576.0    // 2^20: degcnt = cnt*2^20 + sum_w (exact split)

// ---------------- scratch (static device globals; no allocation) ----------------
__device__ double g_degcnt[N_NODES];                  // packed: cnt*2^20 + sum_w
__device__ float  g_dinv[N_NODES];
__device__ __align__(16) float g_y[N_NODES * YPAD];   // (x@W)*dinv, 128B rows
__device__ __align__(8) float2 g_ecsr[(long long)N_NODES * SLOTS]; // (src_bits, w)
__device__ float  g_pmax[R_POOL][N_GRAPHS * EMBED];
__device__ float  g_psum[R_POOL][N_GRAPHS * EMBED];
__device__ float  g_gcnt[R_POOL * N_GRAPHS];
__device__ int    g_idx64;

// ---------------- init + dtype detect ------------------------------------------
// int64 detection: little-endian values < 2^31 => odd 32-bit words all zero.
__global__ void k_init(const int* ei) {
    int i = blockIdx.x * blockDim.x + threadIdx.x;
    if (i == 0) {
        unsigned v = (unsigned)ei[1] | (unsigned)ei[3] | (unsigned)ei[5] |
                     (unsigned)ei[7] | (unsigned)ei[9] | (unsigned)ei[11];
        g_idx64 = (v == 0u) ? 1 : 0;
    }
    if (i < N_NODES) g_degcnt[i] = 0.0;
    if (i < R_POOL * N_GRAPHS * EMBED) {
        (&g_pmax[0][0])[i] = 0.0f;
        (&g_psum[0][0])[i] = 0.0f;
    }
    if (i < R_POOL * N_GRAPHS) g_gcnt[i] = 0.0f;
}

// ---------------- scatter: 4 edges/thread, ONE packed double atomic each -------
// old = cnt*2^20 + sum_w  ->  slot = (int)(old * 2^-20) exact (sum_w < 96).
__device__ __forceinline__ void scat1(int src, int dst, float we) {
    double o = atomicAdd(&g_degcnt[dst], (double)we + CNT_SCALE);
    int p = (int)(o * (1.0 / CNT_SCALE));
    if (p < SLOTS)
        g_ecsr[(long long)dst * SLOTS + p] = make_float2(__int_as_float(src), we);
}

__global__ void k_scatter(const void* ei, const float* __restrict__ w) {
    int t = blockIdx.x * blockDim.x + threadIdx.x;
    if (t >= N_EDGES / 4) return;
    int src[4], dst[4];
    if (g_idx64) {
        longlong2 s0 = ((const longlong2*)ei)[2 * t];
        longlong2 s1 = ((const longlong2*)ei)[2 * t + 1];
        const long long* dbase = (const long long*)ei + N_EDGES;
        longlong2 d0 = ((const longlong2*)dbase)[2 * t];
        longlong2 d1 = ((const longlong2*)dbase)[2 * t + 1];
        src[0] = (int)s0.x; src[1] = (int)s0.y; src[2] = (int)s1.x; src[3] = (int)s1.y;
        dst[0] = (int)d0.x; dst[1] = (int)d0.y; dst[2] = (int)d1.x; dst[3] = (int)d1.y;
    } else {
        int4 s = ((const int4*)ei)[t];
        int4 d = ((const int4*)((const int*)ei + N_EDGES))[t];
        src[0] = s.x; src[1] = s.y; src[2] = s.z; src[3] = s.w;
        dst[0] = d.x; dst[1] = d.y; dst[2] = d.z; dst[3] = d.w;
    }
    float4 wv = ((const float4*)w)[t];
    scat1(src[0], dst[0], wv.x);
    scat1(src[1], dst[1], wv.y);
    scat1(src[2], dst[2], wv.z);
    scat1(src[3], dst[3], wv.w);
}

// ---------------- y = (x @ W) * dinv[row], smem-tiled x ------------------------
// 128 threads/block, 128-row tile staged through smem with coalesced gmem loads
// (row pitch 33 float4s -> only 4-way LDS conflict in compute phase).
#define XTP 33   // float4 pitch per row in smem
__global__ void k_xw(const float* __restrict__ x, const float* __restrict__ W) {
    __shared__ float  Ws[N_FEAT * EMBED];
    __shared__ float4 Xs[128 * XTP];
    int t = threadIdx.x;
    for (int i = t; i < N_FEAT * EMBED; i += 128) Ws[i] = W[i];

    int base_row = blockIdx.x * 128;
    int nrows = min(128, N_NODES - base_row);
    const float4* xg = (const float4*)(x + (long long)base_row * N_FEAT);
    for (int i4 = t; i4 < nrows * 32; i4 += 128) {
        int r = i4 >> 5, c = i4 & 31;
        Xs[r * XTP + c] = xg[i4];           // gmem side fully coalesced
    }
    __syncthreads();

    int row = base_row + t;
    if (row >= N_NODES) return;
    const float4* xr = Xs + t * XTP;
    float4 acc[5];
#pragma unroll
    for (int q = 0; q < 5; q++) acc[q] = make_float4(0.f, 0.f, 0.f, 0.f);

#pragma unroll 4
    for (int k4 = 0; k4 < N_FEAT / 4; k4++) {
        float4 xv = xr[k4];
        float xs[4] = {xv.x, xv.y, xv.z, xv.w};
#pragma unroll
        for (int kk = 0; kk < 4; kk++) {
            const float4* wrow = (const float4*)(Ws + (4 * k4 + kk) * EMBED);
#pragma unroll
            for (int q = 0; q < 5; q++) {
                float4 wv = wrow[q];
                acc[q].x += xs[kk] * wv.x;
                acc[q].y += xs[kk] * wv.y;
                acc[q].z += xs[kk] * wv.z;
                acc[q].w += xs[kk] * wv.w;
            }
        }
    }
    double dv = g_degcnt[row];
    int c = (int)(dv * (1.0 / CNT_SCALE));
    float wsum = (float)(dv - (double)c * CNT_SCALE);
    float dinv = rsqrtf(1.0f + wsum);          // +1 = self-loop weight
    g_dinv[row] = dinv;
    float4* yo = (float4*)(g_y + row * YPAD);
#pragma unroll
    for (int q = 0; q < 5; q++) {
        acc[q].x *= dinv; acc[q].y *= dinv; acc[q].z *= dinv; acc[q].w *= dinv;
        yo[q] = acc[q];
    }
}

// ---------------- fused gather + node epilogue + pooling -----------------------
// One warp per node. 6 edge sub-groups x 5 lanes, 4x unrolled: 24 edges per
// iteration -> 24 independent y-line loads in flight.
__global__ void k_gather(const float* __restrict__ b, const void* batch) {
    int gw   = (blockIdx.x * blockDim.x + threadIdx.x) >> 5;
    int lane = threadIdx.x & 31;
    if (gw >= N_NODES) return;
    int n = gw;
    long long start = (long long)n * SLOTS;
    int len = min((int)(g_degcnt[n] * (1.0 / CNT_SCALE)), SLOTS);
    int sub = lane / 5;
    int q   = lane - sub * 5;
    bool lact = (sub < 6);

    const float4* y4 = (const float4*)g_y;
    float4 acc = make_float4(0.f, 0.f, 0.f, 0.f);

    // four prefetched 6-edge batches (padding slots never read: guarded by len)
    float2 p0 = make_float2(0.f, 0.f), p1 = p0, p2 = p0, p3 = p0;
    if (lact) {
        if (sub < len)      p0 = __ldcs(&g_ecsr[start + sub]);
        if (6  + sub < len) p1 = __ldcs(&g_ecsr[start + 6  + sub]);
        if (12 + sub < len) p2 = __ldcs(&g_ecsr[start + 12 + sub]);
        if (18 + sub < len) p3 = __ldcs(&g_ecsr[start + 18 + sub]);
    }

    for (int base = 0; base < len; base += 24) {
        float2 c0 = p0, c1 = p1, c2 = p2, c3 = p3;
        p0 = make_float2(0.f, 0.f); p1 = p0; p2 = p0; p3 = p0;
        if (lact) {
            int n0 = base + 24 + sub;
            if (n0      < len) p0 = __ldcs(&g_ecsr[start + n0]);
            if (n0 + 6  < len) p1 = __ldcs(&g_ecsr[start + n0 + 6]);
            if (n0 + 12 < len) p2 = __ldcs(&g_ecsr[start + n0 + 12]);
            if (n0 + 18 < len) p3 = __ldcs(&g_ecsr[start + n0 + 18]);
        }
        int s0 = __float_as_int(c0.x);         // 0 when inactive (w=0)
        int s1 = __float_as_int(c1.x);
        int s2 = __float_as_int(c2.x);
        int s3 = __float_as_int(c3.x);
        float4 y0 = y4[s0 * (YPAD / 4) + q];
        float4 y1 = y4[s1 * (YPAD / 4) + q];
        float4 y2 = y4[s2 * (YPAD / 4) + q];
        float4 y3 = y4[s3 * (YPAD / 4) + q];
        acc.x += c0.y * y0.x + c1.y * y1.x + c2.y * y2.x + c3.y * y3.x;
        acc.y += c0.y * y0.y + c1.y * y1.y + c2.y * y2.y + c3.y * y3.y;
        acc.z += c0.y * y0.z + c1.y * y1.z + c2.y * y2.z + c3.y * y3.z;
        acc.w += c0.y * y0.w + c1.y * y1.w + c2.y * y2.w + c3.y * y3.w;
    }

    // reduce the 6 sub-groups into lanes 0..4
    float t0;
#define RED6(c)                                        \
    c += __shfl_down_sync(0xffffffffu, c, 15);         \
    t0 = __shfl_down_sync(0xffffffffu, c, 5);          \
    c += __shfl_down_sync(0xffffffffu, c, 10);         \
    c += t0;
    RED6(acc.x) RED6(acc.y) RED6(acc.z) RED6(acc.w)
#undef RED6

    float dinv = g_dinv[n];
    float4 v = make_float4(0.f, 0.f, 0.f, 0.f);
    float sq = 0.0f;
    if (lane < 5) {
        float4 ys = y4[n * (YPAD / 4) + lane];            // self-loop: dinv * y_n
        float4 bb = ((const float4*)b)[lane];
        v.x = dinv * (acc.x + ys.x) + bb.x;
        v.y = dinv * (acc.y + ys.y) + bb.y;
        v.z = dinv * (acc.z + ys.z) + bb.z;
        v.w = dinv * (acc.w + ys.w) + bb.w;
        sq = v.x * v.x + v.y * v.y + v.z * v.z + v.w * v.w;
    }
    // sum sq over lanes 0..4 within the 8-lane group (lanes 5..7 contribute 0)
    sq += __shfl_xor_sync(0xffffffffu, sq, 1);
    sq += __shfl_xor_sync(0xffffffffu, sq, 2);
    sq += __shfl_xor_sync(0xffffffffu, sq, 4);
    float inv = 1.0f / fmaxf(sqrtf(sq), 1e-12f);

    int g;
    if (g_idx64) g = (int)((const long long*)batch)[n];
    else         g = ((const int*)batch)[n];
    int r = gw & (R_POOL - 1);
    if (lane < 5) {
        float4 em;
        em.x = fmaxf(v.x * inv, 0.0f);
        em.y = fmaxf(v.y * inv, 0.0f);
        em.z = fmaxf(v.z * inv, 0.0f);
        em.w = fmaxf(v.w * inv, 0.0f);
        int bi = g * EMBED + 4 * lane;
        // em >= 0 -> uint compare == float compare; replica init 0 matches ref.
        atomicMax((unsigned int*)&g_pmax[r][bi + 0], __float_as_uint(em.x));
        atomicMax((unsigned int*)&g_pmax[r][bi + 1], __float_as_uint(em.y));
        atomicMax((unsigned int*)&g_pmax[r][bi + 2], __float_as_uint(em.z));
        atomicMax((unsigned int*)&g_pmax[r][bi + 3], __float_as_uint(em.w));
        atomicAdd(&g_psum[r][bi + 0], em.x);
        atomicAdd(&g_psum[r][bi + 1], em.y);
        atomicAdd(&g_psum[r][bi + 2], em.z);
        atomicAdd(&g_psum[r][bi + 3], em.w);
    }
    if (lane == 0) atomicAdd(&g_gcnt[r * N_GRAPHS + g], 1.0f);
}

// ---------------- head: reduce replicas; pooled @ lin_W + lin_b ----------------
__global__ void k_final(const float* __restrict__ lin_W,
                        const float* __restrict__ lin_b,
                        float* __restrict__ out) {
    __shared__ float pooled[N_GRAPHS * 2 * EMBED];
    __shared__ float scnt[N_GRAPHS];
    int t = threadIdx.x;
    if (t < N_GRAPHS) {
        float c = 0.0f;
#pragma unroll
        for (int r = 0; r < R_POOL; r++) c += g_gcnt[r * N_GRAPHS + t];
        scnt[t] = fmaxf(c, 1.0f);
    }
    __syncthreads();
    for (int i = t; i < N_GRAPHS * EMBED; i += blockDim.x) {
        float mx = 0.0f, sm = 0.0f;
#pragma unroll
        for (int r = 0; r < R_POOL; r++) {
            mx = fmaxf(mx, g_pmax[r][i]);
            sm += g_psum[r][i];
        }
        int g = i / EMBED;
        int j = i - g * EMBED;
        pooled[g * 2 * EMBED + j] = mx;
        pooled[g * 2 * EMBED + EMBED + j] = sm / scnt[g];
    }
    __syncthreads();
    if (t < N_GRAPHS * N_CLASSES) {
        int g = t / N_CLASSES;
        int k = t - g * N_CLASSES;
        float s = lin_b[k];
#pragma unroll
        for (int j = 0; j < 2 * EMBED; j++)
            s += pooled[g * 2 * EMBED + j] * lin_W[j * N_CLASSES + k];
        out[t] = s;
    }
}

// ---------------- launch --------------------------------------------------------
extern "C" void kernel_launch(void* const* d_in, const int* in_sizes, int n_in,
                              void* d_out, int out_size) {
    const float* x     = (const float*)d_in[0];
    const void*  ei    = d_in[1];
    const float* ew    = (const float*)d_in[2];
    const void*  batch = d_in[3];
    const float* W     = (const float*)d_in[4];
    const float* b     = (const float*)d_in[5];
    const float* linW  = (const float*)d_in[6];
    const float* linb  = (const float*)d_in[7];
    float* out = (float*)d_out;

    const int T = 256;

    k_init   <<<(N_NODES + T - 1) / T, T>>>((const int*)ei);
    k_scatter<<<(N_EDGES / 4 + T - 1) / T, T>>>(ei, ew);
    k_xw     <<<(N_NODES + 127) / 128, 128>>>(x, W);
    k_gather <<<(N_NODES * 32 + T - 1) / T, T>>>(b, batch);
    k_final  <<<1, 640>>>(linW, linb, out);
}

// round 15
// speedup vs baseline: 1.2151x; 1.2151x over previous
#include <cuda_runtime.h>

#define N_NODES   100000
#define N_EDGES   3200000
#define N_FEAT    128
#define EMBED     20
#define N_CLASSES 10
#define N_GRAPHS  64
#define R_POOL    16
#define SLOTS     128          // padded CSR row capacity; P(deg>=128) ~ e^-81
#define YPAD      32           // y row padded to 32 floats = 128 B = 1 cache line

#define CNT_SCALE 1048576.0    // 2^20: degcnt = cnt*2^20 + sum_w (exact split)

// ---------------- scratch (static device globals; no allocation) ----------------
__device__ double g_degcnt[N_NODES];                  // packed: cnt*2^20 + sum_w
__device__ float  g_dinv[N_NODES];
__device__ __align__(16) float g_y[N_NODES * YPAD];   // (x@W)*dinv, 128B rows
__device__ __align__(8) float2 g_ecsr[(long long)N_NODES * SLOTS]; // (src_bits, w)
__device__ float  g_pmax[R_POOL][N_GRAPHS * EMBED];
__device__ float  g_psum[R_POOL][N_GRAPHS * EMBED];
__device__ float  g_gcnt[R_POOL * N_GRAPHS];
__device__ int    g_idx64;

// ---------------- init + dtype detect ------------------------------------------
// int64 detection: little-endian values < 2^31 => odd 32-bit words all zero.
__global__ void k_init(const int* ei) {
    int i = blockIdx.x * blockDim.x + threadIdx.x;
    if (i == 0) {
        unsigned v = (unsigned)ei[1] | (unsigned)ei[3] | (unsigned)ei[5] |
                     (unsigned)ei[7] | (unsigned)ei[9] | (unsigned)ei[11];
        g_idx64 = (v == 0u) ? 1 : 0;
    }
    if (i < N_NODES) g_degcnt[i] = 0.0;
    if (i < R_POOL * N_GRAPHS * EMBED) {
        (&g_pmax[0][0])[i] = 0.0f;
        (&g_psum[0][0])[i] = 0.0f;
    }
    if (i < R_POOL * N_GRAPHS) g_gcnt[i] = 0.0f;
}

// ---------------- scatter: 2 edges/thread, ONE packed double atomic each -------
// old = cnt*2^20 + sum_w  ->  slot = (int)(old * 2^-20) exact (sum_w < 128).
__global__ void k_scatter(const void* ei, const float* __restrict__ w) {
    int t = blockIdx.x * blockDim.x + threadIdx.x;
    if (t >= N_EDGES / 2) return;
    int src0, src1, dst0, dst1;
    if (g_idx64) {
        longlong2 s = ((const longlong2*)ei)[t];
        longlong2 d = ((const longlong2*)((const long long*)ei + N_EDGES))[t];
        src0 = (int)s.x; src1 = (int)s.y;
        dst0 = (int)d.x; dst1 = (int)d.y;
    } else {
        int2 s = ((const int2*)ei)[t];
        int2 d = ((const int2*)((const int*)ei + N_EDGES))[t];
        src0 = s.x; src1 = s.y;
        dst0 = d.x; dst1 = d.y;
    }
    float2 wv = ((const float2*)w)[t];

    double o0 = atomicAdd(&g_degcnt[dst0], (double)wv.x + CNT_SCALE);
    int p0 = (int)(o0 * (1.0 / CNT_SCALE));
    if (p0 < SLOTS)
        g_ecsr[(long long)dst0 * SLOTS + p0] = make_float2(__int_as_float(src0), wv.x);

    double o1 = atomicAdd(&g_degcnt[dst1], (double)wv.y + CNT_SCALE);
    int p1 = (int)(o1 * (1.0 / CNT_SCALE));
    if (p1 < SLOTS)
        g_ecsr[(long long)dst1 * SLOTS + p1] = make_float2(__int_as_float(src1), wv.y);
}

// ---------------- y = (x @ W) * dinv[row]; extract dinv from packed degcnt -----
__global__ void k_xw(const float* __restrict__ x, const float* __restrict__ W) {
    __shared__ float Ws[N_FEAT * EMBED];
    for (int i = threadIdx.x; i < N_FEAT * EMBED; i += blockDim.x) Ws[i] = W[i];
    __syncthreads();

    int row = blockIdx.x * blockDim.x + threadIdx.x;
    if (row >= N_NODES) return;
    const float4* xr = (const float4*)(x + (long long)row * N_FEAT);
    float4 acc[5];
#pragma unroll
    for (int q = 0; q < 5; q++) acc[q] = make_float4(0.f, 0.f, 0.f, 0.f);

#pragma unroll 4
    for (int k4 = 0; k4 < N_FEAT / 4; k4++) {
        float4 xv = xr[k4];
        float xs[4] = {xv.x, xv.y, xv.z, xv.w};
#pragma unroll
        for (int kk = 0; kk < 4; kk++) {
            const float4* wrow = (const float4*)(Ws + (4 * k4 + kk) * EMBED);
#pragma unroll
            for (int q = 0; q < 5; q++) {
                float4 wv = wrow[q];
                acc[q].x += xs[kk] * wv.x;
                acc[q].y += xs[kk] * wv.y;
                acc[q].z += xs[kk] * wv.z;
                acc[q].w += xs[kk] * wv.w;
            }
        }
    }
    double dv = g_degcnt[row];
    int c = (int)(dv * (1.0 / CNT_SCALE));
    float wsum = (float)(dv - (double)c * CNT_SCALE);
    float dinv = rsqrtf(1.0f + wsum);          // +1 = self-loop weight
    g_dinv[row] = dinv;
    float4* yo = (float4*)(g_y + row * YPAD);
#pragma unroll
    for (int q = 0; q < 5; q++) {
        acc[q].x *= dinv; acc[q].y *= dinv; acc[q].z *= dinv; acc[q].w *= dinv;
        yo[q] = acc[q];
    }
}

// ---------------- fused gather + node epilogue + block-aggregated pooling ------
// One warp per node, 8 nodes per block (grid divides N_NODES exactly: 12500x8).
// Gather mainloop identical to R11 (2x unroll, measured best). Pooling now
// aggregates the block's 8 node embeddings in smem (batch is sorted -> mostly
// one graph per block) and flushes ~one set of atomics per block instead of 8.
__global__ void k_gather(const float* __restrict__ b, const void* batch) {
    __shared__ float s_em[8][EMBED];
    __shared__ int   s_g[8];

    int gw   = (blockIdx.x * blockDim.x + threadIdx.x) >> 5;
    int lane = threadIdx.x & 31;
    int wblk = threadIdx.x >> 5;
    int n = gw;                       // always < N_NODES (exact division)
    long long start = (long long)n * SLOTS;
    int len = min((int)(g_degcnt[n] * (1.0 / CNT_SCALE)), SLOTS);
    int sub = lane / 5;
    int q   = lane - sub * 5;
    bool lact = (sub < 6);

    const float4* y4 = (const float4*)g_y;
    float4 acc = make_float4(0.f, 0.f, 0.f, 0.f);

    // two prefetched 6-edge batches (padding slots never read: guarded by len)
    float2 p0 = make_float2(0.f, 0.f);
    float2 p1 = make_float2(0.f, 0.f);
    if (lact) {
        if (sub < len)     p0 = __ldcs(&g_ecsr[start + sub]);
        if (6 + sub < len) p1 = __ldcs(&g_ecsr[start + 6 + sub]);
    }

    for (int base = 0; base < len; base += 12) {
        float2 c0 = p0, c1 = p1;
        int n0 = base + 12 + sub;
        int n1 = base + 18 + sub;
        p0 = make_float2(0.f, 0.f);
        p1 = make_float2(0.f, 0.f);
        if (lact && n0 < len) p0 = __ldcs(&g_ecsr[start + n0]);
        if (lact && n1 < len) p1 = __ldcs(&g_ecsr[start + n1]);

        int s0 = __float_as_int(c0.x);         // 0 when inactive (w=0)
        int s1 = __float_as_int(c1.x);
        float4 y0 = y4[s0 * (YPAD / 4) + q];
        float4 y1 = y4[s1 * (YPAD / 4) + q];
        acc.x += c0.y * y0.x + c1.y * y1.x;
        acc.y += c0.y * y0.y + c1.y * y1.y;
        acc.z += c0.y * y0.z + c1.y * y1.z;
        acc.w += c0.y * y0.w + c1.y * y1.w;
    }

    // reduce the 6 sub-groups into lanes 0..4
    float t0;
#define RED6(c)                                        \
    c += __shfl_down_sync(0xffffffffu, c, 15);         \
    t0 = __shfl_down_sync(0xffffffffu, c, 5);          \
    c += __shfl_down_sync(0xffffffffu, c, 10);         \
    c += t0;
    RED6(acc.x) RED6(acc.y) RED6(acc.z) RED6(acc.w)
#undef RED6

    float dinv = g_dinv[n];
    float4 v = make_float4(0.f, 0.f, 0.f, 0.f);
    float sq = 0.0f;
    if (lane < 5) {
        float4 ys = y4[n * (YPAD / 4) + lane];            // self-loop: dinv * y_n
        float4 bb = ((const float4*)b)[lane];
        v.x = dinv * (acc.x + ys.x) + bb.x;
        v.y = dinv * (acc.y + ys.y) + bb.y;
        v.z = dinv * (acc.z + ys.z) + bb.z;
        v.w = dinv * (acc.w + ys.w) + bb.w;
        sq = v.x * v.x + v.y * v.y + v.z * v.z + v.w * v.w;
    }
    // sum sq over lanes 0..4 within the 8-lane group (lanes 5..7 contribute 0)
    sq += __shfl_xor_sync(0xffffffffu, sq, 1);
    sq += __shfl_xor_sync(0xffffffffu, sq, 2);
    sq += __shfl_xor_sync(0xffffffffu, sq, 4);
    float inv = 1.0f / fmaxf(sqrtf(sq), 1e-12f);

    int g;
    if (g_idx64) g = (int)((const long long*)batch)[n];
    else         g = ((const int*)batch)[n];

    // stage this node's embedding + graph id in smem
    if (lane < 5) {
        int fi = 4 * lane;
        s_em[wblk][fi + 0] = fmaxf(v.x * inv, 0.0f);
        s_em[wblk][fi + 1] = fmaxf(v.y * inv, 0.0f);
        s_em[wblk][fi + 2] = fmaxf(v.z * inv, 0.0f);
        s_em[wblk][fi + 3] = fmaxf(v.w * inv, 0.0f);
    }
    if (lane == 0) s_g[wblk] = g;
    __syncthreads();

    // run-length merge over the 8 warps (batch sorted -> few runs), flush
    // one atomic pair per (run, feature). threads 0..19 own features.
    int t = threadIdx.x;
    int r = blockIdx.x & (R_POOL - 1);
    if (t < EMBED) {
        int gcur = s_g[0];
        float mx = s_em[0][t];
        float sm = mx;
#pragma unroll
        for (int wv = 1; wv < 8; wv++) {
            int gg = s_g[wv];
            float val = s_em[wv][t];
            if (gg != gcur) {
                // em >= 0 -> uint compare == float compare; init 0 matches ref.
                atomicMax((unsigned int*)&g_pmax[r][gcur * EMBED + t],
                          __float_as_uint(mx));
                atomicAdd(&g_psum[r][gcur * EMBED + t], sm);
                gcur = gg; mx = val; sm = val;
            } else {
                mx = fmaxf(mx, val);
                sm += val;
            }
        }
        atomicMax((unsigned int*)&g_pmax[r][gcur * EMBED + t], __float_as_uint(mx));
        atomicAdd(&g_psum[r][gcur * EMBED + t], sm);
    } else if (t == EMBED) {
        int gcur = s_g[0];
        float c = 1.0f;
#pragma unroll
        for (int wv = 1; wv < 8; wv++) {
            int gg = s_g[wv];
            if (gg != gcur) {
                atomicAdd(&g_gcnt[r * N_GRAPHS + gcur], c);
                gcur = gg; c = 1.0f;
            } else c += 1.0f;
        }
        atomicAdd(&g_gcnt[r * N_GRAPHS + gcur], c);
    }
}

// ---------------- head: reduce replicas; pooled @ lin_W + lin_b ----------------
__global__ void k_final(const float* __restrict__ lin_W,
                        const float* __restrict__ lin_b,
                        float* __restrict__ out) {
    __shared__ float pooled[N_GRAPHS * 2 * EMBED];
    __shared__ float scnt[N_GRAPHS];
    int t = threadIdx.x;
    if (t < N_GRAPHS) {
        float c = 0.0f;
#pragma unroll
        for (int r = 0; r < R_POOL; r++) c += g_gcnt[r * N_GRAPHS + t];
        scnt[t] = fmaxf(c, 1.0f);
    }
    __syncthreads();
    for (int i = t; i < N_GRAPHS * EMBED; i += blockDim.x) {
        float mx = 0.0f, sm = 0.0f;
#pragma unroll
        for (int r = 0; r < R_POOL; r++) {
            mx = fmaxf(mx, g_pmax[r][i]);
            sm += g_psum[r][i];
        }
        int g = i / EMBED;
        int j = i - g * EMBED;
        pooled[g * 2 * EMBED + j] = mx;
        pooled[g * 2 * EMBED + EMBED + j] = sm / scnt[g];
    }
    __syncthreads();
    if (t < N_GRAPHS * N_CLASSES) {
        int g = t / N_CLASSES;
        int k = t - g * N_CLASSES;
        float s = lin_b[k];
#pragma unroll
        for (int j = 0; j < 2 * EMBED; j++)
            s += pooled[g * 2 * EMBED + j] * lin_W[j * N_CLASSES + k];
        out[t] = s;
    }
}

// ---------------- launch --------------------------------------------------------
extern "C" void kernel_launch(void* const* d_in, const int* in_sizes, int n_in,
                              void* d_out, int out_size) {
    const float* x     = (const float*)d_in[0];
    const void*  ei    = d_in[1];
    const float* ew    = (const float*)d_in[2];
    const void*  batch = d_in[3];
    const float* W     = (const float*)d_in[4];
    const float* b     = (const float*)d_in[5];
    const float* linW  = (const float*)d_in[6];
    const float* linb  = (const float*)d_in[7];
    float* out = (float*)d_out;

    const int T = 256;

    k_init   <<<(N_NODES + T - 1) / T, T>>>((const int*)ei);
    k_scatter<<<(N_EDGES / 2 + T - 1) / T, T>>>(ei, ew);
    k_xw     <<<(N_NODES + 127) / 128, 128>>>(x, W);
    k_gather <<<N_NODES / 8, 256>>>(b, batch);   // 12500 blocks x 8 warps, exact
    k_final  <<<1, 640>>>(linW, linb, out);
}